// round 14
// baseline (speedup 1.0000x reference)
#include <cuda_runtime.h>
#include <cuda_fp16.h>
#include <cstdint>

#define B_   2
#define S_   2048
#define D_   1024
#define H_   16
#define DK_  64
#define EPS_ 0.1f
#define M_ROWS (B_ * S_)          // 4096
#define N_QKV  (3 * D_)           // 3072

// Scratch (allocation-free requirement -> __device__ globals)
__device__ __half g_qkvh[M_ROWS * N_QKV];
__device__ __half g_qkvl[M_ROWS * N_QKV];
__device__ __half g_ah[M_ROWS * D_];
__device__ __half g_al[M_ROWS * D_];
__device__ __half g_wqh[N_QKV * D_];
__device__ __half g_wql[N_QKV * D_];
__device__ __half g_woh[D_ * D_];
__device__ __half g_wol[D_ * D_];

// ---------------------------------------------------------------------------
// helpers
// ---------------------------------------------------------------------------
__device__ __forceinline__ uint32_t smem_u32(const void* p) {
    return (uint32_t)__cvta_generic_to_shared(p);
}
__device__ __forceinline__ void ldsm_x4(uint32_t& r0, uint32_t& r1, uint32_t& r2,
                                        uint32_t& r3, uint32_t addr) {
    asm volatile("ldmatrix.sync.aligned.m8n8.x4.shared.b16 {%0,%1,%2,%3}, [%4];"
                 : "=r"(r0), "=r"(r1), "=r"(r2), "=r"(r3) : "r"(addr));
}
__device__ __forceinline__ void ldsm_x2(uint32_t& r0, uint32_t& r1, uint32_t addr) {
    asm volatile("ldmatrix.sync.aligned.m8n8.x2.shared.b16 {%0,%1}, [%2];"
                 : "=r"(r0), "=r"(r1) : "r"(addr));
}
__device__ __forceinline__ void ldsm_x2_t(uint32_t& r0, uint32_t& r1, uint32_t addr) {
    asm volatile("ldmatrix.sync.aligned.m8n8.x2.trans.shared.b16 {%0,%1}, [%2];"
                 : "=r"(r0), "=r"(r1) : "r"(addr));
}
// main term: fp16 inputs, fp32 accumulate
__device__ __forceinline__ void mma_m(float c[4], const uint32_t a[4],
                                      const uint32_t b[2]) {
    asm volatile(
        "mma.sync.aligned.m16n8k16.row.col.f32.f16.f16.f32 "
        "{%0,%1,%2,%3}, {%4,%5,%6,%7}, {%8,%9}, {%0,%1,%2,%3};"
        : "+f"(c[0]), "+f"(c[1]), "+f"(c[2]), "+f"(c[3])
        : "r"(a[0]), "r"(a[1]), "r"(a[2]), "r"(a[3]), "r"(b[0]), "r"(b[1]));
}
// correction terms: fp16 inputs, fp16 accumulate (full-rate)
__device__ __forceinline__ void mma_c(uint32_t c[2], const uint32_t a[4],
                                      const uint32_t b[2]) {
    asm volatile(
        "mma.sync.aligned.m16n8k16.row.col.f16.f16.f16.f16 "
        "{%0,%1}, {%2,%3,%4,%5}, {%6,%7}, {%0,%1};"
        : "+r"(c[0]), "+r"(c[1])
        : "r"(a[0]), "r"(a[1]), "r"(a[2]), "r"(a[3]), "r"(b[0]), "r"(b[1]));
}
__device__ __forceinline__ void add_h2(float& x, float& y, uint32_t h) {
    const float2 f = __half22float2(*(const __half2*)&h);
    x += f.x; y += f.y;
}
__device__ __forceinline__ uint32_t pack_hi2(float x, float y) {
    __half2 t = __floats2half2_rn(x, y);
    return *(uint32_t*)&t;
}
__device__ __forceinline__ uint32_t pack_lo2(float x, float y) {
    float hx = __half2float(__float2half(x));
    float hy = __half2float(__float2half(y));
    __half2 t = __floats2half2_rn(x - hx, y - hy);
    return *(uint32_t*)&t;
}
__device__ __forceinline__ void cpasync16(uint32_t saddr, const void* g) {
    asm volatile("cp.async.ca.shared.global [%0], [%1], 16;" :: "r"(saddr), "l"(g));
}
__device__ __forceinline__ void cpcommit() {
    asm volatile("cp.async.commit_group;");
}
template <int N>
__device__ __forceinline__ void cpwait() {
    asm volatile("cp.async.wait_group %0;" :: "n"(N));
}

// ---------------------------------------------------------------------------
// fp32 -> (hi,lo) fp16 split
// ---------------------------------------------------------------------------
__global__ void split_kernel(const float* __restrict__ in,
                             __half* __restrict__ hi,
                             __half* __restrict__ lo, int n4) {
    int i = blockIdx.x * blockDim.x + threadIdx.x;
    if (i >= n4) return;
    float4 f = ((const float4*)in)[i];
    uint2 hh, ll;
    hh.x = pack_hi2(f.x, f.y); hh.y = pack_hi2(f.z, f.w);
    ll.x = pack_lo2(f.x, f.y); ll.y = pack_lo2(f.z, f.w);
    ((uint2*)hi)[i] = hh;
    ((uint2*)lo)[i] = ll;
}

// ---------------------------------------------------------------------------
// guard clamp
// ---------------------------------------------------------------------------
__device__ __forceinline__ float guard_clamp(
    float v, int m, int n,
    const float* __restrict__ akmin, const float* __restrict__ akmax,
    const float* __restrict__ avmin, const float* __restrict__ avmax) {
    const int c = n >> 10;
    const int b  = m >> 11;
    const int h  = (n & 1023) >> 6;
    const int ch = n & 63;
    const int ai = ((b << 4) + h) * 64 + ch;
    const float amin = (c == 1) ? akmin[ai] : avmin[ai];
    const float amax = (c == 1) ? akmax[ai] : avmax[ai];
    float lo = fmaxf(v - EPS_, amin);
    float hi = fminf(v + EPS_, amax);
    lo = fminf(lo, hi);
    return fmaxf(lo, fminf(v, hi));
}

// ---------------------------------------------------------------------------
// Split-fp16 tensor-core GEMM:  C[M,N] = A[M,K] @ B[N,K]^T + bias
// Main term f32-accum, correction terms f16-accum (full-rate pipe).
// Block 128x128, 4 warps (2x2), warp tile 64x64, BK=16, 4-stage ring.
// ---------------------------------------------------------------------------
#define GSTG    24576            // bytes per stage
#define OFF_AL  6144
#define OFF_BH  12288
#define OFF_BL  18432
#define GEMM_SMEM (4 * GSTG)     // 98304 bytes

template <int MODE>
__global__ __launch_bounds__(128, 2) void gemm_f16s_kernel(
    const __half* __restrict__ Ah, const __half* __restrict__ Al,
    const __half* __restrict__ Bh, const __half* __restrict__ Bl,
    const float* __restrict__ bias,
    float* __restrict__ C,
    __half* __restrict__ Ch, __half* __restrict__ Cl,
    int M, int N, int K,
    const float* __restrict__ akmin, const float* __restrict__ akmax,
    const float* __restrict__ avmin, const float* __restrict__ avmax)
{
    extern __shared__ __half smem[];

    const int tid  = threadIdx.x;
    const int wid  = tid >> 5;
    const int lane = tid & 31;
    const int warp_m = (wid & 1) * 64;
    const int warp_n = (wid >> 1) * 64;
    const int bm = blockIdx.y * 128;
    const int bn = blockIdx.x * 128;

    const int KS = K >> 4;     // 64
    const uint32_t sb0 = smem_u32(smem);

    auto load_stage = [&](int ks, int buf) {
        const uint32_t sb = sb0 + buf * GSTG;
        const int k0 = ks * 16;
#pragma unroll
        for (int i = 0; i < 2; i++) {
            const int chk = tid + i * 128;
            const int r = chk >> 1, c = (chk & 1) * 8;
            const uint32_t sa = sb + (r * 24 + c) * 2;
            const size_t goA = (size_t)(bm + r) * K + k0 + c;
            cpasync16(sa,          Ah + goA);
            cpasync16(sa + OFF_AL, Al + goA);
            const size_t goB = (size_t)(bn + r) * K + k0 + c;
            cpasync16(sa + OFF_BH, Bh + goB);
            cpasync16(sa + OFF_BL, Bl + goB);
        }
        cpcommit();
    };

    float c[4][8][4];
    uint32_t cc[4][8][2];
#pragma unroll
    for (int mt = 0; mt < 4; mt++)
#pragma unroll
        for (int nt = 0; nt < 8; nt++) {
#pragma unroll
            for (int e = 0; e < 4; e++) c[mt][nt][e] = 0.0f;
            cc[mt][nt][0] = 0u; cc[mt][nt][1] = 0u;
        }

    load_stage(0, 0);
    load_stage(1, 1);
    load_stage(2, 2);

    const int ar = lane & 15, ac = (lane >> 4) << 3;
    const int br = lane & 7,  bc = ((lane >> 3) & 1) << 3;

    for (int ks = 0; ks < KS; ks++) {
        const int buf = ks & 3;
        cpwait<2>();
        __syncthreads();
        const uint32_t sb = sb0 + buf * GSTG;

        uint32_t afh[4][4], afl[4][4];
#pragma unroll
        for (int mt = 0; mt < 4; mt++) {
            const uint32_t aoff = ((warp_m + mt * 16 + ar) * 24 + ac) * 2;
            ldsm_x4(afh[mt][0], afh[mt][1], afh[mt][2], afh[mt][3], sb + aoff);
            ldsm_x4(afl[mt][0], afl[mt][1], afl[mt][2], afl[mt][3],
                    sb + OFF_AL + aoff);
        }
#pragma unroll
        for (int nt = 0; nt < 8; nt++) {
            uint32_t bh[2], bl[2];
            const uint32_t boff = ((warp_n + nt * 8 + br) * 24 + bc) * 2;
            ldsm_x2(bh[0], bh[1], sb + OFF_BH + boff);
            ldsm_x2(bl[0], bl[1], sb + OFF_BL + boff);
#pragma unroll
            for (int mt = 0; mt < 4; mt++) {
                mma_m(c[mt][nt], afh[mt], bh);
                mma_c(cc[mt][nt], afh[mt], bl);
                mma_c(cc[mt][nt], afl[mt], bh);
            }
        }
        if (ks + 3 < KS) load_stage(ks + 3, (ks + 3) & 3);
        else cpcommit();
    }

    // Epilogue: fold f16 corrections, add bias, clamp/scale, write
    const int g = lane >> 2, t = lane & 3;
#pragma unroll
    for (int mt = 0; mt < 4; mt++) {
#pragma unroll
        for (int nt = 0; nt < 8; nt++) {
            float cf0 = c[mt][nt][0], cf1 = c[mt][nt][1];
            float cf2 = c[mt][nt][2], cf3 = c[mt][nt][3];
            add_h2(cf0, cf1, cc[mt][nt][0]);
            add_h2(cf2, cf3, cc[mt][nt][1]);
            const int n0 = bn + warp_n + nt * 8 + t * 2;
            const float b0 = bias[n0], b1 = bias[n0 + 1];
            float vv[4] = { cf0 + b0, cf1 + b1, cf2 + b0, cf3 + b1 };
#pragma unroll
            for (int half = 0; half < 2; half++) {
                const int m = bm + warp_m + mt * 16 + g + half * 8;
                float v0 = vv[half * 2 + 0];
                float v1 = vv[half * 2 + 1];
                if (MODE == 1) {
                    if ((n0 >> 10) == 0) { v0 *= 0.125f; v1 *= 0.125f; }
                    else {
                        v0 = guard_clamp(v0, m, n0,     akmin, akmax, avmin, avmax);
                        v1 = guard_clamp(v1, m, n0 + 1, akmin, akmax, avmin, avmax);
                    }
                    *(uint32_t*)&Ch[(size_t)m * N + n0] = pack_hi2(v0, v1);
                    *(uint32_t*)&Cl[(size_t)m * N + n0] = pack_lo2(v0, v1);
                } else {
                    *(float2*)&C[(size_t)m * N + n0] = make_float2(v0, v1);
                }
            }
        }
    }
}

// ---------------------------------------------------------------------------
// Tensor-core flash attention over pre-split fp16 QKV.
// Main terms f32-accum, corrections f16-accum drained per phase.
// ---------------------------------------------------------------------------
#define STR_ 72

__global__ __launch_bounds__(128) void attn_tc_kernel(
    const __half* __restrict__ qkvh,
    const __half* __restrict__ qkvl,
    __half* __restrict__ oh, __half* __restrict__ ol)
{
    extern __shared__ __half sb[];
    __half* sQh = sb;
    __half* sQl = sQh + 64 * STR_;
    __half* sKh = sQl + 64 * STR_;
    __half* sKl = sKh + 64 * STR_;
    __half* sVh = sKl + 64 * STR_;
    __half* sVl = sVh + 64 * STR_;

    const int qt = blockIdx.x, h = blockIdx.y, b = blockIdx.z;
    const int tid = threadIdx.x, w = tid >> 5, lane = tid & 31;
    const int g = lane >> 2, t = lane & 3;

#pragma unroll
    for (int it = 0; it < 4; it++) {
        const int idx = tid + it * 128;
        const int r = idx >> 3, c8 = (idx & 7) << 3;
        const size_t gb = ((size_t)(b * S_ + qt * 64 + r) * 3) * 1024 + h * 64 + c8;
        *(uint4*)&sQh[r * STR_ + c8] = *(const uint4*)(qkvh + gb);
        *(uint4*)&sQl[r * STR_ + c8] = *(const uint4*)(qkvl + gb);
    }
    __syncthreads();

    uint32_t aqh[4][4], aql[4][4];
    const int ar = lane & 15, ac8 = (lane >> 4) << 3;
#pragma unroll
    for (int k = 0; k < 4; k++) {
        const int roff = (w * 16 + ar) * STR_ + ac8 + k * 16;
        ldsm_x4(aqh[k][0], aqh[k][1], aqh[k][2], aqh[k][3], smem_u32(&sQh[roff]));
        ldsm_x4(aql[k][0], aql[k][1], aql[k][2], aql[k][3], smem_u32(&sQl[roff]));
    }

    float o[8][4];
#pragma unroll
    for (int dt = 0; dt < 8; dt++)
#pragma unroll
        for (int e = 0; e < 4; e++) o[dt][e] = 0.0f;
    float m0 = -1e30f, m1 = -1e30f, l0 = 0.0f, l1 = 0.0f;

    const int kr = lane & 7, kc = ((lane >> 3) & 1) << 3;
    const int vr = lane & 15;

    for (int kt = 0; kt < S_ / 64; kt++) {
        __syncthreads();
#pragma unroll
        for (int it = 0; it < 4; it++) {
            const int idx = tid + it * 128;
            const int r = idx >> 3, c8 = (idx & 7) << 3;
            const size_t gb =
                ((size_t)(b * S_ + kt * 64 + r) * 3) * 1024 + h * 64 + c8;
            *(uint4*)&sKh[r * STR_ + c8] = *(const uint4*)(qkvh + gb + 1024);
            *(uint4*)&sKl[r * STR_ + c8] = *(const uint4*)(qkvl + gb + 1024);
            *(uint4*)&sVh[r * STR_ + c8] = *(const uint4*)(qkvh + gb + 2048);
            *(uint4*)&sVl[r * STR_ + c8] = *(const uint4*)(qkvl + gb + 2048);
        }
        __syncthreads();

        // ---- S = Q @ K^T: main f32-acc + f16-acc corrections ----
        float sc[8][4];
        uint32_t scc[8][2];
#pragma unroll
        for (int nt = 0; nt < 8; nt++) {
#pragma unroll
            for (int e = 0; e < 4; e++) sc[nt][e] = 0.0f;
            scc[nt][0] = 0u; scc[nt][1] = 0u;
        }
#pragma unroll
        for (int k = 0; k < 4; k++) {
#pragma unroll
            for (int nt = 0; nt < 8; nt++) {
                uint32_t bh[2], bl[2];
                const int boff = (nt * 8 + kr) * STR_ + kc + k * 16;
                ldsm_x2(bh[0], bh[1], smem_u32(&sKh[boff]));
                ldsm_x2(bl[0], bl[1], smem_u32(&sKl[boff]));
                mma_m(sc[nt], aqh[k], bh);
                mma_c(scc[nt], aqh[k], bl);
                mma_c(scc[nt], aql[k], bh);
            }
        }
#pragma unroll
        for (int nt = 0; nt < 8; nt++) {
            add_h2(sc[nt][0], sc[nt][1], scc[nt][0]);
            add_h2(sc[nt][2], sc[nt][3], scc[nt][1]);
        }

        // ---- online softmax ----
        float mx0 = -1e30f, mx1 = -1e30f;
#pragma unroll
        for (int nt = 0; nt < 8; nt++) {
            mx0 = fmaxf(mx0, fmaxf(sc[nt][0], sc[nt][1]));
            mx1 = fmaxf(mx1, fmaxf(sc[nt][2], sc[nt][3]));
        }
        mx0 = fmaxf(mx0, __shfl_xor_sync(0xffffffffu, mx0, 1));
        mx0 = fmaxf(mx0, __shfl_xor_sync(0xffffffffu, mx0, 2));
        mx1 = fmaxf(mx1, __shfl_xor_sync(0xffffffffu, mx1, 1));
        mx1 = fmaxf(mx1, __shfl_xor_sync(0xffffffffu, mx1, 2));
        const float mn0 = fmaxf(m0, mx0), mn1 = fmaxf(m1, mx1);
        const float c0 = __expf(m0 - mn0), c1 = __expf(m1 - mn1);
        float rs0 = 0.0f, rs1 = 0.0f;
#pragma unroll
        for (int nt = 0; nt < 8; nt++) {
            sc[nt][0] = __expf(sc[nt][0] - mn0);
            sc[nt][1] = __expf(sc[nt][1] - mn0);
            sc[nt][2] = __expf(sc[nt][2] - mn1);
            sc[nt][3] = __expf(sc[nt][3] - mn1);
            rs0 += sc[nt][0] + sc[nt][1];
            rs1 += sc[nt][2] + sc[nt][3];
        }
        rs0 += __shfl_xor_sync(0xffffffffu, rs0, 1);
        rs0 += __shfl_xor_sync(0xffffffffu, rs0, 2);
        rs1 += __shfl_xor_sync(0xffffffffu, rs1, 1);
        rs1 += __shfl_xor_sync(0xffffffffu, rs1, 2);
        l0 = l0 * c0 + rs0;
        l1 = l1 * c1 + rs1;
        m0 = mn0; m1 = mn1;
#pragma unroll
        for (int dt = 0; dt < 8; dt++) {
            o[dt][0] *= c0; o[dt][1] *= c0;
            o[dt][2] *= c1; o[dt][3] *= c1;
        }

        // ---- O += P @ V: main f32-acc + f16-acc corrections (drained per kt) ----
        uint32_t oc[8][2];
#pragma unroll
        for (int dt = 0; dt < 8; dt++) { oc[dt][0] = 0u; oc[dt][1] = 0u; }
#pragma unroll
        for (int kq = 0; kq < 4; kq++) {
            uint32_t ph[4], pl[4];
            ph[0] = pack_hi2(sc[2 * kq][0], sc[2 * kq][1]);
            ph[1] = pack_hi2(sc[2 * kq][2], sc[2 * kq][3]);
            ph[2] = pack_hi2(sc[2 * kq + 1][0], sc[2 * kq + 1][1]);
            ph[3] = pack_hi2(sc[2 * kq + 1][2], sc[2 * kq + 1][3]);
            pl[0] = pack_lo2(sc[2 * kq][0], sc[2 * kq][1]);
            pl[1] = pack_lo2(sc[2 * kq][2], sc[2 * kq][3]);
            pl[2] = pack_lo2(sc[2 * kq + 1][0], sc[2 * kq + 1][1]);
            pl[3] = pack_lo2(sc[2 * kq + 1][2], sc[2 * kq + 1][3]);
#pragma unroll
            for (int dt = 0; dt < 8; dt++) {
                uint32_t bvh[2], bvl[2];
                const int voff = (kq * 16 + vr) * STR_ + dt * 8;
                ldsm_x2_t(bvh[0], bvh[1], smem_u32(&sVh[voff]));
                ldsm_x2_t(bvl[0], bvl[1], smem_u32(&sVl[voff]));
                mma_m(o[dt], ph, bvh);
                mma_c(oc[dt], ph, bvl);
                mma_c(oc[dt], pl, bvh);
            }
        }
#pragma unroll
        for (int dt = 0; dt < 8; dt++) {
            add_h2(o[dt][0], o[dt][1], oc[dt][0]);
            add_h2(o[dt][2], o[dt][3], oc[dt][1]);
        }
    }

    const float inv0 = 1.0f / l0, inv1 = 1.0f / l1;
    const int r0 = qt * 64 + w * 16 + g;
    const int r1 = r0 + 8;
#pragma unroll
    for (int dt = 0; dt < 8; dt++) {
        const int d0 = h * 64 + dt * 8 + t * 2;
        const float x0 = o[dt][0] * inv0, x1 = o[dt][1] * inv0;
        const float y0 = o[dt][2] * inv1, y1 = o[dt][3] * inv1;
        const size_t p0 = (size_t)(b * S_ + r0) * 1024 + d0;
        const size_t p1 = (size_t)(b * S_ + r1) * 1024 + d0;
        *(uint32_t*)&oh[p0] = pack_hi2(x0, x1);
        *(uint32_t*)&ol[p0] = pack_lo2(x0, x1);
        *(uint32_t*)&oh[p1] = pack_hi2(y0, y1);
        *(uint32_t*)&ol[p1] = pack_lo2(y0, y1);
    }
}

// ---------------------------------------------------------------------------
extern "C" void kernel_launch(void* const* d_in, const int* in_sizes, int n_in,
                              void* d_out, int out_size)
{
    const float* x      = (const float*)d_in[0];
    const float* qkv_w  = (const float*)d_in[1];
    const float* qkv_b  = (const float*)d_in[2];
    const float* out_w  = (const float*)d_in[3];
    const float* out_b  = (const float*)d_in[4];
    const float* akmin  = (const float*)d_in[5];
    const float* akmax  = (const float*)d_in[6];
    const float* avmin  = (const float*)d_in[7];
    const float* avmax  = (const float*)d_in[8];
    float* out = (float*)d_out;

    __half *qkvh, *qkvl, *ah, *al, *wqh, *wql, *woh, *wol;
    cudaGetSymbolAddress((void**)&qkvh, g_qkvh);
    cudaGetSymbolAddress((void**)&qkvl, g_qkvl);
    cudaGetSymbolAddress((void**)&ah,  g_ah);
    cudaGetSymbolAddress((void**)&al,  g_al);
    cudaGetSymbolAddress((void**)&wqh, g_wqh);
    cudaGetSymbolAddress((void**)&wql, g_wql);
    cudaGetSymbolAddress((void**)&woh, g_woh);
    cudaGetSymbolAddress((void**)&wol, g_wol);

    const int attn_smem = 6 * 64 * STR_ * (int)sizeof(__half);   // 55296
    cudaFuncSetAttribute(gemm_f16s_kernel<1>,
                         cudaFuncAttributeMaxDynamicSharedMemorySize, GEMM_SMEM);
    cudaFuncSetAttribute(gemm_f16s_kernel<0>,
                         cudaFuncAttributeMaxDynamicSharedMemorySize, GEMM_SMEM);
    cudaFuncSetAttribute(attn_tc_kernel,
                         cudaFuncAttributeMaxDynamicSharedMemorySize, attn_smem);

    // 0) split fp32 inputs -> hi/lo fp16
    split_kernel<<<(M_ROWS * D_ / 4 + 255) / 256, 256>>>(x, ah, al, M_ROWS * D_ / 4);
    split_kernel<<<(N_QKV * D_ / 4 + 255) / 256, 256>>>(qkv_w, wqh, wql, N_QKV * D_ / 4);
    split_kernel<<<(D_ * D_ / 4 + 255) / 256, 256>>>(out_w, woh, wol, D_ * D_ / 4);

    // 1) QKV projection + bias + q-scale + guard-clamp -> split fp16 QKV
    {
        dim3 grid(N_QKV / 128, M_ROWS / 128);   // 24 x 32
        gemm_f16s_kernel<1><<<grid, 128, GEMM_SMEM>>>(
            ah, al, wqh, wql, qkv_b, nullptr, qkvh, qkvl, M_ROWS, N_QKV, D_,
            akmin, akmax, avmin, avmax);
    }

    // 2) Tensor-core flash attention (split-fp16 out into ah/al)
    {
        dim3 grid(S_ / 64, H_, B_);
        attn_tc_kernel<<<grid, 128, attn_smem>>>(qkvh, qkvl, ah, al);
    }

    // 3) Output projection (fp32 result)
    {
        dim3 grid(D_ / 128, M_ROWS / 128);      // 8 x 32
        gemm_f16s_kernel<0><<<grid, 128, GEMM_SMEM>>>(
            ah, al, woh, wol, out_b, out, nullptr, nullptr, M_ROWS, D_, D_,
            nullptr, nullptr, nullptr, nullptr);
    }
}

// round 15
// speedup vs baseline: 1.4267x; 1.4267x over previous
#include <cuda_runtime.h>
#include <cuda_fp16.h>
#include <cstdint>

#define B_   2
#define S_   2048
#define D_   1024
#define H_   16
#define DK_  64
#define EPS_ 0.1f
#define M_ROWS (B_ * S_)          // 4096
#define N_QKV  (3 * D_)           // 3072

// Scratch (allocation-free requirement -> __device__ globals)
__device__ __half g_qkvh[M_ROWS * N_QKV];
__device__ __half g_qkvl[M_ROWS * N_QKV];
__device__ __half g_ah[M_ROWS * D_];
__device__ __half g_al[M_ROWS * D_];
__device__ __half g_wqh[N_QKV * D_];
__device__ __half g_woh[D_ * D_];

// ---------------------------------------------------------------------------
// helpers
// ---------------------------------------------------------------------------
__device__ __forceinline__ uint32_t smem_u32(const void* p) {
    return (uint32_t)__cvta_generic_to_shared(p);
}
__device__ __forceinline__ void ldsm_x4(uint32_t& r0, uint32_t& r1, uint32_t& r2,
                                        uint32_t& r3, uint32_t addr) {
    asm volatile("ldmatrix.sync.aligned.m8n8.x4.shared.b16 {%0,%1,%2,%3}, [%4];"
                 : "=r"(r0), "=r"(r1), "=r"(r2), "=r"(r3) : "r"(addr));
}
__device__ __forceinline__ void ldsm_x2(uint32_t& r0, uint32_t& r1, uint32_t addr) {
    asm volatile("ldmatrix.sync.aligned.m8n8.x2.shared.b16 {%0,%1}, [%2];"
                 : "=r"(r0), "=r"(r1) : "r"(addr));
}
__device__ __forceinline__ void ldsm_x2_t(uint32_t& r0, uint32_t& r1, uint32_t addr) {
    asm volatile("ldmatrix.sync.aligned.m8n8.x2.trans.shared.b16 {%0,%1}, [%2];"
                 : "=r"(r0), "=r"(r1) : "r"(addr));
}
__device__ __forceinline__ void mma_m(float c[4], const uint32_t a[4],
                                      const uint32_t b[2]) {
    asm volatile(
        "mma.sync.aligned.m16n8k16.row.col.f32.f16.f16.f32 "
        "{%0,%1,%2,%3}, {%4,%5,%6,%7}, {%8,%9}, {%0,%1,%2,%3};"
        : "+f"(c[0]), "+f"(c[1]), "+f"(c[2]), "+f"(c[3])
        : "r"(a[0]), "r"(a[1]), "r"(a[2]), "r"(a[3]), "r"(b[0]), "r"(b[1]));
}
__device__ __forceinline__ uint32_t pack_hi2(float x, float y) {
    __half2 t = __floats2half2_rn(x, y);
    return *(uint32_t*)&t;
}
__device__ __forceinline__ uint32_t pack_lo2(float x, float y) {
    float hx = __half2float(__float2half(x));
    float hy = __half2float(__float2half(y));
    __half2 t = __floats2half2_rn(x - hx, y - hy);
    return *(uint32_t*)&t;
}
__device__ __forceinline__ void cpasync16(uint32_t saddr, const void* g) {
    asm volatile("cp.async.ca.shared.global [%0], [%1], 16;" :: "r"(saddr), "l"(g));
}
__device__ __forceinline__ void cpcommit() {
    asm volatile("cp.async.commit_group;");
}
template <int N>
__device__ __forceinline__ void cpwait() {
    asm volatile("cp.async.wait_group %0;" :: "n"(N));
}

// ---------------------------------------------------------------------------
// fp32 -> (hi,lo) fp16 split; lo may be null (hi-only, for 2-term B operands)
// ---------------------------------------------------------------------------
__global__ void split_kernel(const float* __restrict__ in,
                             __half* __restrict__ hi,
                             __half* __restrict__ lo, int n4) {
    int i = blockIdx.x * blockDim.x + threadIdx.x;
    if (i >= n4) return;
    float4 f = ((const float4*)in)[i];
    uint2 hh;
    hh.x = pack_hi2(f.x, f.y); hh.y = pack_hi2(f.z, f.w);
    ((uint2*)hi)[i] = hh;
    if (lo) {
        uint2 ll;
        ll.x = pack_lo2(f.x, f.y); ll.y = pack_lo2(f.z, f.w);
        ((uint2*)lo)[i] = ll;
    }
}

// ---------------------------------------------------------------------------
// guard clamp
// ---------------------------------------------------------------------------
__device__ __forceinline__ float guard_clamp(
    float v, int m, int n,
    const float* __restrict__ akmin, const float* __restrict__ akmax,
    const float* __restrict__ avmin, const float* __restrict__ avmax) {
    const int c = n >> 10;
    const int b  = m >> 11;
    const int h  = (n & 1023) >> 6;
    const int ch = n & 63;
    const int ai = ((b << 4) + h) * 64 + ch;
    const float amin = (c == 1) ? akmin[ai] : avmin[ai];
    const float amax = (c == 1) ? akmax[ai] : avmax[ai];
    float lo = fmaxf(v - EPS_, amin);
    float hi = fminf(v + EPS_, amax);
    lo = fminf(lo, hi);
    return fmaxf(lo, fminf(v, hi));
}

// ---------------------------------------------------------------------------
// 2-term split-fp16 GEMM:  C = (Ah + Al) @ Bh^T + bias  (B lo dropped)
// Block 128x128, 4 warps (2x2), warp tile 64x64, BK=16, 4-stage cp.async ring.
// Stage layout (BYTES): Ah@0 | Al@6144 | Bh@12288; stage 18432 B; 4x = 73728.
// ---------------------------------------------------------------------------
#define GSTG    18432
#define OFF_AL  6144
#define OFF_BH  12288
#define GEMM_SMEM (4 * GSTG)     // 73728 bytes -> 2 CTAs/SM

template <int MODE>
__global__ __launch_bounds__(128, 2) void gemm_f16s_kernel(
    const __half* __restrict__ Ah, const __half* __restrict__ Al,
    const __half* __restrict__ Bh,
    const float* __restrict__ bias,
    float* __restrict__ C,
    __half* __restrict__ Ch, __half* __restrict__ Cl,
    int M, int N, int K,
    const float* __restrict__ akmin, const float* __restrict__ akmax,
    const float* __restrict__ avmin, const float* __restrict__ avmax)
{
    extern __shared__ __half smem[];

    const int tid  = threadIdx.x;
    const int wid  = tid >> 5;
    const int lane = tid & 31;
    const int warp_m = (wid & 1) * 64;
    const int warp_n = (wid >> 1) * 64;
    const int bm = blockIdx.y * 128;
    const int bn = blockIdx.x * 128;

    const int KS = K >> 4;     // 64
    const uint32_t sb0 = smem_u32(smem);

    auto load_stage = [&](int ks, int buf) {
        const uint32_t sb = sb0 + buf * GSTG;
        const int k0 = ks * 16;
#pragma unroll
        for (int i = 0; i < 2; i++) {
            const int chk = tid + i * 128;          // 0..255
            const int r = chk >> 1, c = (chk & 1) * 8;
            const uint32_t sa = sb + (r * 24 + c) * 2;
            const size_t goA = (size_t)(bm + r) * K + k0 + c;
            cpasync16(sa,          Ah + goA);
            cpasync16(sa + OFF_AL, Al + goA);
            const size_t goB = (size_t)(bn + r) * K + k0 + c;
            cpasync16(sa + OFF_BH, Bh + goB);
        }
        cpcommit();
    };

    float c[4][8][4];
#pragma unroll
    for (int mt = 0; mt < 4; mt++)
#pragma unroll
        for (int nt = 0; nt < 8; nt++)
#pragma unroll
            for (int e = 0; e < 4; e++) c[mt][nt][e] = 0.0f;

    load_stage(0, 0);
    load_stage(1, 1);
    load_stage(2, 2);

    const int ar = lane & 15, ac = (lane >> 4) << 3;
    const int br = lane & 7,  bc = ((lane >> 3) & 1) << 3;

    for (int ks = 0; ks < KS; ks++) {
        const int buf = ks & 3;
        cpwait<2>();
        __syncthreads();
        const uint32_t sb = sb0 + buf * GSTG;

        uint32_t afh[4][4], afl[4][4];
#pragma unroll
        for (int mt = 0; mt < 4; mt++) {
            const uint32_t aoff = ((warp_m + mt * 16 + ar) * 24 + ac) * 2;
            ldsm_x4(afh[mt][0], afh[mt][1], afh[mt][2], afh[mt][3], sb + aoff);
            ldsm_x4(afl[mt][0], afl[mt][1], afl[mt][2], afl[mt][3],
                    sb + OFF_AL + aoff);
        }
#pragma unroll
        for (int nt = 0; nt < 8; nt++) {
            uint32_t bh[2];
            const uint32_t boff = ((warp_n + nt * 8 + br) * 24 + bc) * 2;
            ldsm_x2(bh[0], bh[1], sb + OFF_BH + boff);
#pragma unroll
            for (int mt = 0; mt < 4; mt++) {
                mma_m(c[mt][nt], afh[mt], bh);
                mma_m(c[mt][nt], afl[mt], bh);
            }
        }
        if (ks + 3 < KS) load_stage(ks + 3, (ks + 3) & 3);
        else cpcommit();
    }

    // Epilogue
    const int g = lane >> 2, t = lane & 3;
#pragma unroll
    for (int mt = 0; mt < 4; mt++) {
#pragma unroll
        for (int nt = 0; nt < 8; nt++) {
            const int n0 = bn + warp_n + nt * 8 + t * 2;
            const float b0 = bias[n0], b1 = bias[n0 + 1];
#pragma unroll
            for (int half = 0; half < 2; half++) {
                const int m = bm + warp_m + mt * 16 + g + half * 8;
                float v0 = c[mt][nt][half * 2 + 0] + b0;
                float v1 = c[mt][nt][half * 2 + 1] + b1;
                if (MODE == 1) {
                    if ((n0 >> 10) == 0) { v0 *= 0.125f; v1 *= 0.125f; }
                    else {
                        v0 = guard_clamp(v0, m, n0,     akmin, akmax, avmin, avmax);
                        v1 = guard_clamp(v1, m, n0 + 1, akmin, akmax, avmin, avmax);
                    }
                    *(uint32_t*)&Ch[(size_t)m * N + n0] = pack_hi2(v0, v1);
                    *(uint32_t*)&Cl[(size_t)m * N + n0] = pack_lo2(v0, v1);
                } else {
                    *(float2*)&C[(size_t)m * N + n0] = make_float2(v0, v1);
                }
            }
        }
    }
}

// ---------------------------------------------------------------------------
// 2-term tensor-core flash attention:
//   S = (Qh + Ql) @ Kh^T      (K lo dropped)
//   O = (Ph + Pl) @ Vh        (V lo dropped)
// smem: Qh, Ql, Kh, Vh each [64][72] fp16 = 36864 B.
// ---------------------------------------------------------------------------
#define STR_ 72

__global__ __launch_bounds__(128) void attn_tc_kernel(
    const __half* __restrict__ qkvh,
    const __half* __restrict__ qkvl,
    __half* __restrict__ oh, __half* __restrict__ ol)
{
    extern __shared__ __half sb[];
    __half* sQh = sb;
    __half* sQl = sQh + 64 * STR_;
    __half* sKh = sQl + 64 * STR_;
    __half* sVh = sKh + 64 * STR_;

    const int qt = blockIdx.x, h = blockIdx.y, b = blockIdx.z;
    const int tid = threadIdx.x, w = tid >> 5, lane = tid & 31;
    const int g = lane >> 2, t = lane & 3;

#pragma unroll
    for (int it = 0; it < 4; it++) {
        const int idx = tid + it * 128;
        const int r = idx >> 3, c8 = (idx & 7) << 3;
        const size_t gb = ((size_t)(b * S_ + qt * 64 + r) * 3) * 1024 + h * 64 + c8;
        *(uint4*)&sQh[r * STR_ + c8] = *(const uint4*)(qkvh + gb);
        *(uint4*)&sQl[r * STR_ + c8] = *(const uint4*)(qkvl + gb);
    }
    __syncthreads();

    uint32_t aqh[4][4], aql[4][4];
    const int ar = lane & 15, ac8 = (lane >> 4) << 3;
#pragma unroll
    for (int k = 0; k < 4; k++) {
        const int roff = (w * 16 + ar) * STR_ + ac8 + k * 16;
        ldsm_x4(aqh[k][0], aqh[k][1], aqh[k][2], aqh[k][3], smem_u32(&sQh[roff]));
        ldsm_x4(aql[k][0], aql[k][1], aql[k][2], aql[k][3], smem_u32(&sQl[roff]));
    }

    float o[8][4];
#pragma unroll
    for (int dt = 0; dt < 8; dt++)
#pragma unroll
        for (int e = 0; e < 4; e++) o[dt][e] = 0.0f;
    float m0 = -1e30f, m1 = -1e30f, l0 = 0.0f, l1 = 0.0f;

    const int kr = lane & 7, kc = ((lane >> 3) & 1) << 3;
    const int vr = lane & 15;

    for (int kt = 0; kt < S_ / 64; kt++) {
        __syncthreads();
#pragma unroll
        for (int it = 0; it < 4; it++) {
            const int idx = tid + it * 128;
            const int r = idx >> 3, c8 = (idx & 7) << 3;
            const size_t gb =
                ((size_t)(b * S_ + kt * 64 + r) * 3) * 1024 + h * 64 + c8;
            *(uint4*)&sKh[r * STR_ + c8] = *(const uint4*)(qkvh + gb + 1024);
            *(uint4*)&sVh[r * STR_ + c8] = *(const uint4*)(qkvh + gb + 2048);
        }
        __syncthreads();

        // ---- S = (Qh + Ql) @ Kh^T ----
        float sc[8][4];
#pragma unroll
        for (int nt = 0; nt < 8; nt++)
#pragma unroll
            for (int e = 0; e < 4; e++) sc[nt][e] = 0.0f;
#pragma unroll
        for (int k = 0; k < 4; k++) {
#pragma unroll
            for (int nt = 0; nt < 8; nt++) {
                uint32_t bh[2];
                const int boff = (nt * 8 + kr) * STR_ + kc + k * 16;
                ldsm_x2(bh[0], bh[1], smem_u32(&sKh[boff]));
                mma_m(sc[nt], aqh[k], bh);
                mma_m(sc[nt], aql[k], bh);
            }
        }

        // ---- online softmax ----
        float mx0 = -1e30f, mx1 = -1e30f;
#pragma unroll
        for (int nt = 0; nt < 8; nt++) {
            mx0 = fmaxf(mx0, fmaxf(sc[nt][0], sc[nt][1]));
            mx1 = fmaxf(mx1, fmaxf(sc[nt][2], sc[nt][3]));
        }
        mx0 = fmaxf(mx0, __shfl_xor_sync(0xffffffffu, mx0, 1));
        mx0 = fmaxf(mx0, __shfl_xor_sync(0xffffffffu, mx0, 2));
        mx1 = fmaxf(mx1, __shfl_xor_sync(0xffffffffu, mx1, 1));
        mx1 = fmaxf(mx1, __shfl_xor_sync(0xffffffffu, mx1, 2));
        const float mn0 = fmaxf(m0, mx0), mn1 = fmaxf(m1, mx1);
        const float c0 = __expf(m0 - mn0), c1 = __expf(m1 - mn1);
        float rs0 = 0.0f, rs1 = 0.0f;
#pragma unroll
        for (int nt = 0; nt < 8; nt++) {
            sc[nt][0] = __expf(sc[nt][0] - mn0);
            sc[nt][1] = __expf(sc[nt][1] - mn0);
            sc[nt][2] = __expf(sc[nt][2] - mn1);
            sc[nt][3] = __expf(sc[nt][3] - mn1);
            rs0 += sc[nt][0] + sc[nt][1];
            rs1 += sc[nt][2] + sc[nt][3];
        }
        rs0 += __shfl_xor_sync(0xffffffffu, rs0, 1);
        rs0 += __shfl_xor_sync(0xffffffffu, rs0, 2);
        rs1 += __shfl_xor_sync(0xffffffffu, rs1, 1);
        rs1 += __shfl_xor_sync(0xffffffffu, rs1, 2);
        l0 = l0 * c0 + rs0;
        l1 = l1 * c1 + rs1;
        m0 = mn0; m1 = mn1;
#pragma unroll
        for (int dt = 0; dt < 8; dt++) {
            o[dt][0] *= c0; o[dt][1] *= c0;
            o[dt][2] *= c1; o[dt][3] *= c1;
        }

        // ---- O += (Ph + Pl) @ Vh ----
#pragma unroll
        for (int kq = 0; kq < 4; kq++) {
            uint32_t ph[4], pl[4];
            ph[0] = pack_hi2(sc[2 * kq][0], sc[2 * kq][1]);
            ph[1] = pack_hi2(sc[2 * kq][2], sc[2 * kq][3]);
            ph[2] = pack_hi2(sc[2 * kq + 1][0], sc[2 * kq + 1][1]);
            ph[3] = pack_hi2(sc[2 * kq + 1][2], sc[2 * kq + 1][3]);
            pl[0] = pack_lo2(sc[2 * kq][0], sc[2 * kq][1]);
            pl[1] = pack_lo2(sc[2 * kq][2], sc[2 * kq][3]);
            pl[2] = pack_lo2(sc[2 * kq + 1][0], sc[2 * kq + 1][1]);
            pl[3] = pack_lo2(sc[2 * kq + 1][2], sc[2 * kq + 1][3]);
#pragma unroll
            for (int dt = 0; dt < 8; dt++) {
                uint32_t bvh[2];
                const int voff = (kq * 16 + vr) * STR_ + dt * 8;
                ldsm_x2_t(bvh[0], bvh[1], smem_u32(&sVh[voff]));
                mma_m(o[dt], ph, bvh);
                mma_m(o[dt], pl, bvh);
            }
        }
    }

    const float inv0 = 1.0f / l0, inv1 = 1.0f / l1;
    const int r0 = qt * 64 + w * 16 + g;
    const int r1 = r0 + 8;
#pragma unroll
    for (int dt = 0; dt < 8; dt++) {
        const int d0 = h * 64 + dt * 8 + t * 2;
        const float x0 = o[dt][0] * inv0, x1 = o[dt][1] * inv0;
        const float y0 = o[dt][2] * inv1, y1 = o[dt][3] * inv1;
        const size_t p0 = (size_t)(b * S_ + r0) * 1024 + d0;
        const size_t p1 = (size_t)(b * S_ + r1) * 1024 + d0;
        *(uint32_t*)&oh[p0] = pack_hi2(x0, x1);
        *(uint32_t*)&ol[p0] = pack_lo2(x0, x1);
        *(uint32_t*)&oh[p1] = pack_hi2(y0, y1);
        *(uint32_t*)&ol[p1] = pack_lo2(y0, y1);
    }
}

// ---------------------------------------------------------------------------
extern "C" void kernel_launch(void* const* d_in, const int* in_sizes, int n_in,
                              void* d_out, int out_size)
{
    const float* x      = (const float*)d_in[0];
    const float* qkv_w  = (const float*)d_in[1];
    const float* qkv_b  = (const float*)d_in[2];
    const float* out_w  = (const float*)d_in[3];
    const float* out_b  = (const float*)d_in[4];
    const float* akmin  = (const float*)d_in[5];
    const float* akmax  = (const float*)d_in[6];
    const float* avmin  = (const float*)d_in[7];
    const float* avmax  = (const float*)d_in[8];
    float* out = (float*)d_out;

    __half *qkvh, *qkvl, *ah, *al, *wqh, *woh;
    cudaGetSymbolAddress((void**)&qkvh, g_qkvh);
    cudaGetSymbolAddress((void**)&qkvl, g_qkvl);
    cudaGetSymbolAddress((void**)&ah,  g_ah);
    cudaGetSymbolAddress((void**)&al,  g_al);
    cudaGetSymbolAddress((void**)&wqh, g_wqh);
    cudaGetSymbolAddress((void**)&woh, g_woh);

    const int attn_smem = 4 * 64 * STR_ * (int)sizeof(__half);   // 36864
    cudaFuncSetAttribute(gemm_f16s_kernel<1>,
                         cudaFuncAttributeMaxDynamicSharedMemorySize, GEMM_SMEM);
    cudaFuncSetAttribute(gemm_f16s_kernel<0>,
                         cudaFuncAttributeMaxDynamicSharedMemorySize, GEMM_SMEM);
    cudaFuncSetAttribute(attn_tc_kernel,
                         cudaFuncAttributeMaxDynamicSharedMemorySize, attn_smem);

    // 0) splits: x -> hi+lo; weights -> hi only (2-term B operands)
    split_kernel<<<(M_ROWS * D_ / 4 + 255) / 256, 256>>>(x, ah, al, M_ROWS * D_ / 4);
    split_kernel<<<(N_QKV * D_ / 4 + 255) / 256, 256>>>(qkv_w, wqh, nullptr,
                                                        N_QKV * D_ / 4);
    split_kernel<<<(D_ * D_ / 4 + 255) / 256, 256>>>(out_w, woh, nullptr,
                                                     D_ * D_ / 4);

    // 1) QKV projection + bias + q-scale + guard-clamp -> split fp16 QKV
    {
        dim3 grid(N_QKV / 128, M_ROWS / 128);   // 24 x 32
        gemm_f16s_kernel<1><<<grid, 128, GEMM_SMEM>>>(
            ah, al, wqh, qkv_b, nullptr, qkvh, qkvl, M_ROWS, N_QKV, D_,
            akmin, akmax, avmin, avmax);
    }

    // 2) Tensor-core flash attention (split-fp16 out into ah/al)
    {
        dim3 grid(S_ / 64, H_, B_);
        attn_tc_kernel<<<grid, 128, attn_smem>>>(qkvh, qkvl, ah, al);
    }

    // 3) Output projection (fp32 result)
    {
        dim3 grid(D_ / 128, M_ROWS / 128);      // 8 x 32
        gemm_f16s_kernel<0><<<grid, 128, GEMM_SMEM>>>(
            ah, al, woh, out_b, out, nullptr, nullptr, M_ROWS, D_, D_,
            nullptr, nullptr, nullptr, nullptr);
    }
}

// round 16
// speedup vs baseline: 2.4287x; 1.7024x over previous
#include <cuda_runtime.h>
#include <cuda_fp16.h>
#include <cstdint>

#define B_   2
#define S_   2048
#define D_   1024
#define H_   16
#define DK_  64
#define EPS_ 0.1f
#define M_ROWS (B_ * S_)          // 4096
#define N_QKV  (3 * D_)           // 3072

// Scratch (allocation-free requirement -> __device__ globals)
__device__ __half g_qkv[M_ROWS * N_QKV];   // fp16 QKV (scaled q / clamped k,v)
__device__ __half g_a[M_ROWS * D_];        // fp16 A operand (x, then attn out)
__device__ __half g_wq[N_QKV * D_];
__device__ __half g_wo[D_ * D_];

// ---------------------------------------------------------------------------
// helpers
// ---------------------------------------------------------------------------
__device__ __forceinline__ uint32_t smem_u32(const void* p) {
    return (uint32_t)__cvta_generic_to_shared(p);
}
__device__ __forceinline__ void ldsm_x4(uint32_t& r0, uint32_t& r1, uint32_t& r2,
                                        uint32_t& r3, uint32_t addr) {
    asm volatile("ldmatrix.sync.aligned.m8n8.x4.shared.b16 {%0,%1,%2,%3}, [%4];"
                 : "=r"(r0), "=r"(r1), "=r"(r2), "=r"(r3) : "r"(addr));
}
__device__ __forceinline__ void ldsm_x2(uint32_t& r0, uint32_t& r1, uint32_t addr) {
    asm volatile("ldmatrix.sync.aligned.m8n8.x2.shared.b16 {%0,%1}, [%2];"
                 : "=r"(r0), "=r"(r1) : "r"(addr));
}
__device__ __forceinline__ void ldsm_x2_t(uint32_t& r0, uint32_t& r1, uint32_t addr) {
    asm volatile("ldmatrix.sync.aligned.m8n8.x2.trans.shared.b16 {%0,%1}, [%2];"
                 : "=r"(r0), "=r"(r1) : "r"(addr));
}
__device__ __forceinline__ void mma_m(float c[4], const uint32_t a[4],
                                      const uint32_t b[2]) {
    asm volatile(
        "mma.sync.aligned.m16n8k16.row.col.f32.f16.f16.f32 "
        "{%0,%1,%2,%3}, {%4,%5,%6,%7}, {%8,%9}, {%0,%1,%2,%3};"
        : "+f"(c[0]), "+f"(c[1]), "+f"(c[2]), "+f"(c[3])
        : "r"(a[0]), "r"(a[1]), "r"(a[2]), "r"(a[3]), "r"(b[0]), "r"(b[1]));
}
__device__ __forceinline__ uint32_t pack_h2(float x, float y) {
    __half2 t = __floats2half2_rn(x, y);
    return *(uint32_t*)&t;
}
__device__ __forceinline__ void cpasync16(uint32_t saddr, const void* g) {
    asm volatile("cp.async.ca.shared.global [%0], [%1], 16;" :: "r"(saddr), "l"(g));
}
__device__ __forceinline__ void cpcommit() {
    asm volatile("cp.async.commit_group;");
}
template <int N>
__device__ __forceinline__ void cpwait() {
    asm volatile("cp.async.wait_group %0;" :: "n"(N));
}

// ---------------------------------------------------------------------------
// fp32 -> fp16 convert
// ---------------------------------------------------------------------------
__global__ void cvt_kernel(const float* __restrict__ in,
                           __half* __restrict__ out, int n4) {
    int i = blockIdx.x * blockDim.x + threadIdx.x;
    if (i >= n4) return;
    float4 f = ((const float4*)in)[i];
    uint2 hh;
    hh.x = pack_h2(f.x, f.y); hh.y = pack_h2(f.z, f.w);
    ((uint2*)out)[i] = hh;
}

// ---------------------------------------------------------------------------
// guard clamp
// ---------------------------------------------------------------------------
__device__ __forceinline__ float guard_clamp(
    float v, int m, int n,
    const float* __restrict__ akmin, const float* __restrict__ akmax,
    const float* __restrict__ avmin, const float* __restrict__ avmax) {
    const int c = n >> 10;
    const int b  = m >> 11;
    const int h  = (n & 1023) >> 6;
    const int ch = n & 63;
    const int ai = ((b << 4) + h) * 64 + ch;
    const float amin = (c == 1) ? akmin[ai] : avmin[ai];
    const float amax = (c == 1) ? akmax[ai] : avmax[ai];
    float lo = fmaxf(v - EPS_, amin);
    float hi = fminf(v + EPS_, amax);
    lo = fminf(lo, hi);
    return fmaxf(lo, fminf(v, hi));
}

// ---------------------------------------------------------------------------
// fp16 tensor-core GEMM:  C[M,N] = A[M,K] @ B[N,K]^T + bias  (f32 accum)
// Block 128x128, 4 warps (2x2), warp tile 64x64, BK=16, 4-stage cp.async ring.
// Stage (BYTES): A@0 (6144) | B@6144 (6144); stage 12288; 4x = 49152 B.
// MODE 1: QKV epilogue (q-scale / kv-clamp, fp16 out).  MODE 0: fp32 out.
// ---------------------------------------------------------------------------
#define GSTG    12288
#define OFF_B   6144
#define GEMM_SMEM (4 * GSTG)     // 49152 bytes -> 2 CTAs/SM (reg-limited)

template <int MODE>
__global__ __launch_bounds__(128, 2) void gemm_f16_kernel(
    const __half* __restrict__ A, const __half* __restrict__ Bm,
    const float* __restrict__ bias,
    float* __restrict__ C, __half* __restrict__ Ch,
    int M, int N, int K,
    const float* __restrict__ akmin, const float* __restrict__ akmax,
    const float* __restrict__ avmin, const float* __restrict__ avmax)
{
    extern __shared__ __half smem[];

    const int tid  = threadIdx.x;
    const int wid  = tid >> 5;
    const int lane = tid & 31;
    const int warp_m = (wid & 1) * 64;
    const int warp_n = (wid >> 1) * 64;
    const int bm = blockIdx.y * 128;
    const int bn = blockIdx.x * 128;

    const int KS = K >> 4;     // 64
    const uint32_t sb0 = smem_u32(smem);

    auto load_stage = [&](int ks, int buf) {
        const uint32_t sb = sb0 + buf * GSTG;
        const int k0 = ks * 16;
#pragma unroll
        for (int i = 0; i < 2; i++) {
            const int chk = tid + i * 128;          // 0..255
            const int r = chk >> 1, c = (chk & 1) * 8;
            const uint32_t sa = sb + (r * 24 + c) * 2;
            cpasync16(sa,         A  + (size_t)(bm + r) * K + k0 + c);
            cpasync16(sa + OFF_B, Bm + (size_t)(bn + r) * K + k0 + c);
        }
        cpcommit();
    };

    float c[4][8][4];
#pragma unroll
    for (int mt = 0; mt < 4; mt++)
#pragma unroll
        for (int nt = 0; nt < 8; nt++)
#pragma unroll
            for (int e = 0; e < 4; e++) c[mt][nt][e] = 0.0f;

    load_stage(0, 0);
    load_stage(1, 1);
    load_stage(2, 2);

    const int ar = lane & 15, ac = (lane >> 4) << 3;
    const int br = lane & 7,  bc = ((lane >> 3) & 1) << 3;

    for (int ks = 0; ks < KS; ks++) {
        const int buf = ks & 3;
        cpwait<2>();
        __syncthreads();
        const uint32_t sb = sb0 + buf * GSTG;

        uint32_t af[4][4];
#pragma unroll
        for (int mt = 0; mt < 4; mt++) {
            const uint32_t aoff = ((warp_m + mt * 16 + ar) * 24 + ac) * 2;
            ldsm_x4(af[mt][0], af[mt][1], af[mt][2], af[mt][3], sb + aoff);
        }
#pragma unroll
        for (int nt = 0; nt < 8; nt++) {
            uint32_t bh[2];
            const uint32_t boff = OFF_B + ((warp_n + nt * 8 + br) * 24 + bc) * 2;
            ldsm_x2(bh[0], bh[1], sb + boff);
#pragma unroll
            for (int mt = 0; mt < 4; mt++)
                mma_m(c[mt][nt], af[mt], bh);
        }
        if (ks + 3 < KS) load_stage(ks + 3, (ks + 3) & 3);
        else cpcommit();   // keep commit-count advancing for the tail
    }

    // Epilogue
    const int g = lane >> 2, t = lane & 3;
#pragma unroll
    for (int mt = 0; mt < 4; mt++) {
#pragma unroll
        for (int nt = 0; nt < 8; nt++) {
            const int n0 = bn + warp_n + nt * 8 + t * 2;
            const float b0 = bias[n0], b1 = bias[n0 + 1];
#pragma unroll
            for (int half = 0; half < 2; half++) {
                const int m = bm + warp_m + mt * 16 + g + half * 8;
                float v0 = c[mt][nt][half * 2 + 0] + b0;
                float v1 = c[mt][nt][half * 2 + 1] + b1;
                if (MODE == 1) {
                    if ((n0 >> 10) == 0) { v0 *= 0.125f; v1 *= 0.125f; }
                    else {
                        v0 = guard_clamp(v0, m, n0,     akmin, akmax, avmin, avmax);
                        v1 = guard_clamp(v1, m, n0 + 1, akmin, akmax, avmin, avmax);
                    }
                    *(uint32_t*)&Ch[(size_t)m * N + n0] = pack_h2(v0, v1);
                } else {
                    *(float2*)&C[(size_t)m * N + n0] = make_float2(v0, v1);
                }
            }
        }
    }
}

// ---------------------------------------------------------------------------
// fp16 tensor-core flash attention (f32 accumulators).
// Block = (b,h, 64-row Q tile), 128 threads = 4 warps, warp owns 16 q-rows.
// smem: Q, K, V each [64][72] fp16 = 27648 B.
// ---------------------------------------------------------------------------
#define STR_ 72

__global__ __launch_bounds__(128) void attn_tc_kernel(
    const __half* __restrict__ qkv, __half* __restrict__ oh)
{
    extern __shared__ __half sb[];
    __half* sQ = sb;
    __half* sK = sQ + 64 * STR_;
    __half* sV = sK + 64 * STR_;

    const int qt = blockIdx.x, h = blockIdx.y, b = blockIdx.z;
    const int tid = threadIdx.x, w = tid >> 5, lane = tid & 31;
    const int g = lane >> 2, t = lane & 3;

#pragma unroll
    for (int it = 0; it < 4; it++) {
        const int idx = tid + it * 128;
        const int r = idx >> 3, c8 = (idx & 7) << 3;
        const size_t gb = ((size_t)(b * S_ + qt * 64 + r) * 3) * 1024 + h * 64 + c8;
        *(uint4*)&sQ[r * STR_ + c8] = *(const uint4*)(qkv + gb);
    }
    __syncthreads();

    uint32_t aq[4][4];
    const int ar = lane & 15, ac8 = (lane >> 4) << 3;
#pragma unroll
    for (int k = 0; k < 4; k++) {
        const int roff = (w * 16 + ar) * STR_ + ac8 + k * 16;
        ldsm_x4(aq[k][0], aq[k][1], aq[k][2], aq[k][3], smem_u32(&sQ[roff]));
    }

    float o[8][4];
#pragma unroll
    for (int dt = 0; dt < 8; dt++)
#pragma unroll
        for (int e = 0; e < 4; e++) o[dt][e] = 0.0f;
    float m0 = -1e30f, m1 = -1e30f, l0 = 0.0f, l1 = 0.0f;

    const int kr = lane & 7, kc = ((lane >> 3) & 1) << 3;
    const int vr = lane & 15;

    for (int kt = 0; kt < S_ / 64; kt++) {
        __syncthreads();
#pragma unroll
        for (int it = 0; it < 4; it++) {
            const int idx = tid + it * 128;
            const int r = idx >> 3, c8 = (idx & 7) << 3;
            const size_t gb =
                ((size_t)(b * S_ + kt * 64 + r) * 3) * 1024 + h * 64 + c8;
            *(uint4*)&sK[r * STR_ + c8] = *(const uint4*)(qkv + gb + 1024);
            *(uint4*)&sV[r * STR_ + c8] = *(const uint4*)(qkv + gb + 2048);
        }
        __syncthreads();

        // ---- S = Q @ K^T ----
        float sc[8][4];
#pragma unroll
        for (int nt = 0; nt < 8; nt++)
#pragma unroll
            for (int e = 0; e < 4; e++) sc[nt][e] = 0.0f;
#pragma unroll
        for (int k = 0; k < 4; k++) {
#pragma unroll
            for (int nt = 0; nt < 8; nt++) {
                uint32_t bh[2];
                const int boff = (nt * 8 + kr) * STR_ + kc + k * 16;
                ldsm_x2(bh[0], bh[1], smem_u32(&sK[boff]));
                mma_m(sc[nt], aq[k], bh);
            }
        }

        // ---- online softmax ----
        float mx0 = -1e30f, mx1 = -1e30f;
#pragma unroll
        for (int nt = 0; nt < 8; nt++) {
            mx0 = fmaxf(mx0, fmaxf(sc[nt][0], sc[nt][1]));
            mx1 = fmaxf(mx1, fmaxf(sc[nt][2], sc[nt][3]));
        }
        mx0 = fmaxf(mx0, __shfl_xor_sync(0xffffffffu, mx0, 1));
        mx0 = fmaxf(mx0, __shfl_xor_sync(0xffffffffu, mx0, 2));
        mx1 = fmaxf(mx1, __shfl_xor_sync(0xffffffffu, mx1, 1));
        mx1 = fmaxf(mx1, __shfl_xor_sync(0xffffffffu, mx1, 2));
        const float mn0 = fmaxf(m0, mx0), mn1 = fmaxf(m1, mx1);
        const float c0 = __expf(m0 - mn0), c1 = __expf(m1 - mn1);
        float rs0 = 0.0f, rs1 = 0.0f;
#pragma unroll
        for (int nt = 0; nt < 8; nt++) {
            sc[nt][0] = __expf(sc[nt][0] - mn0);
            sc[nt][1] = __expf(sc[nt][1] - mn0);
            sc[nt][2] = __expf(sc[nt][2] - mn1);
            sc[nt][3] = __expf(sc[nt][3] - mn1);
            rs0 += sc[nt][0] + sc[nt][1];
            rs1 += sc[nt][2] + sc[nt][3];
        }
        rs0 += __shfl_xor_sync(0xffffffffu, rs0, 1);
        rs0 += __shfl_xor_sync(0xffffffffu, rs0, 2);
        rs1 += __shfl_xor_sync(0xffffffffu, rs1, 1);
        rs1 += __shfl_xor_sync(0xffffffffu, rs1, 2);
        l0 = l0 * c0 + rs0;
        l1 = l1 * c1 + rs1;
        m0 = mn0; m1 = mn1;
#pragma unroll
        for (int dt = 0; dt < 8; dt++) {
            o[dt][0] *= c0; o[dt][1] *= c0;
            o[dt][2] *= c1; o[dt][3] *= c1;
        }

        // ---- O += P @ V ----
#pragma unroll
        for (int kq = 0; kq < 4; kq++) {
            uint32_t ph[4];
            ph[0] = pack_h2(sc[2 * kq][0], sc[2 * kq][1]);
            ph[1] = pack_h2(sc[2 * kq][2], sc[2 * kq][3]);
            ph[2] = pack_h2(sc[2 * kq + 1][0], sc[2 * kq + 1][1]);
            ph[3] = pack_h2(sc[2 * kq + 1][2], sc[2 * kq + 1][3]);
#pragma unroll
            for (int dt = 0; dt < 8; dt++) {
                uint32_t bv[2];
                const int voff = (kq * 16 + vr) * STR_ + dt * 8;
                ldsm_x2_t(bv[0], bv[1], smem_u32(&sV[voff]));
                mma_m(o[dt], ph, bv);
            }
        }
    }

    const float inv0 = 1.0f / l0, inv1 = 1.0f / l1;
    const int r0 = qt * 64 + w * 16 + g;
    const int r1 = r0 + 8;
#pragma unroll
    for (int dt = 0; dt < 8; dt++) {
        const int d0 = h * 64 + dt * 8 + t * 2;
        *(uint32_t*)&oh[(size_t)(b * S_ + r0) * 1024 + d0] =
            pack_h2(o[dt][0] * inv0, o[dt][1] * inv0);
        *(uint32_t*)&oh[(size_t)(b * S_ + r1) * 1024 + d0] =
            pack_h2(o[dt][2] * inv1, o[dt][3] * inv1);
    }
}

// ---------------------------------------------------------------------------
extern "C" void kernel_launch(void* const* d_in, const int* in_sizes, int n_in,
                              void* d_out, int out_size)
{
    const float* x      = (const float*)d_in[0];
    const float* qkv_w  = (const float*)d_in[1];
    const float* qkv_b  = (const float*)d_in[2];
    const float* out_w  = (const float*)d_in[3];
    const float* out_b  = (const float*)d_in[4];
    const float* akmin  = (const float*)d_in[5];
    const float* akmax  = (const float*)d_in[6];
    const float* avmin  = (const float*)d_in[7];
    const float* avmax  = (const float*)d_in[8];
    float* out = (float*)d_out;

    __half *qkv, *a, *wq, *wo;
    cudaGetSymbolAddress((void**)&qkv, g_qkv);
    cudaGetSymbolAddress((void**)&a,   g_a);
    cudaGetSymbolAddress((void**)&wq,  g_wq);
    cudaGetSymbolAddress((void**)&wo,  g_wo);

    const int attn_smem = 3 * 64 * STR_ * (int)sizeof(__half);   // 27648
    cudaFuncSetAttribute(gemm_f16_kernel<1>,
                         cudaFuncAttributeMaxDynamicSharedMemorySize, GEMM_SMEM);
    cudaFuncSetAttribute(gemm_f16_kernel<0>,
                         cudaFuncAttributeMaxDynamicSharedMemorySize, GEMM_SMEM);
    cudaFuncSetAttribute(attn_tc_kernel,
                         cudaFuncAttributeMaxDynamicSharedMemorySize, attn_smem);

    // 0) fp32 -> fp16 converts
    cvt_kernel<<<(M_ROWS * D_ / 4 + 255) / 256, 256>>>(x, a, M_ROWS * D_ / 4);
    cvt_kernel<<<(N_QKV * D_ / 4 + 255) / 256, 256>>>(qkv_w, wq, N_QKV * D_ / 4);
    cvt_kernel<<<(D_ * D_ / 4 + 255) / 256, 256>>>(out_w, wo, D_ * D_ / 4);

    // 1) QKV projection + bias + q-scale + guard-clamp -> fp16 QKV
    {
        dim3 grid(N_QKV / 128, M_ROWS / 128);   // 24 x 32
        gemm_f16_kernel<1><<<grid, 128, GEMM_SMEM>>>(
            a, wq, qkv_b, nullptr, qkv, M_ROWS, N_QKV, D_,
            akmin, akmax, avmin, avmax);
    }

    // 2) Tensor-core flash attention (fp16 out into a)
    {
        dim3 grid(S_ / 64, H_, B_);
        attn_tc_kernel<<<grid, 128, attn_smem>>>(qkv, a);
    }

    // 3) Output projection (fp32 result)
    {
        dim3 grid(D_ / 128, M_ROWS / 128);      // 8 x 32
        gemm_f16_kernel<0><<<grid, 128, GEMM_SMEM>>>(
            a, wo, out_b, out, nullptr, M_ROWS, D_, D_,
            nullptr, nullptr, nullptr, nullptr);
    }
}

// round 17
// speedup vs baseline: 2.7049x; 1.1137x over previous
#include <cuda_runtime.h>
#include <cuda_fp16.h>
#include <cstdint>

#define B_   2
#define S_   2048
#define D_   1024
#define H_   16
#define DK_  64
#define EPS_ 0.1f
#define M_ROWS (B_ * S_)          // 4096
#define N_QKV  (3 * D_)           // 3072

// Scratch (allocation-free requirement -> __device__ globals)
__device__ __half g_qkv[M_ROWS * N_QKV];
__device__ __half g_a[M_ROWS * D_];
__device__ __half g_wq[N_QKV * D_];
__device__ __half g_wo[D_ * D_];

// ---------------------------------------------------------------------------
// helpers
// ---------------------------------------------------------------------------
__device__ __forceinline__ uint32_t smem_u32(const void* p) {
    return (uint32_t)__cvta_generic_to_shared(p);
}
__device__ __forceinline__ void ldsm_x4(uint32_t& r0, uint32_t& r1, uint32_t& r2,
                                        uint32_t& r3, uint32_t addr) {
    asm volatile("ldmatrix.sync.aligned.m8n8.x4.shared.b16 {%0,%1,%2,%3}, [%4];"
                 : "=r"(r0), "=r"(r1), "=r"(r2), "=r"(r3) : "r"(addr));
}
__device__ __forceinline__ void ldsm_x2(uint32_t& r0, uint32_t& r1, uint32_t addr) {
    asm volatile("ldmatrix.sync.aligned.m8n8.x2.shared.b16 {%0,%1}, [%2];"
                 : "=r"(r0), "=r"(r1) : "r"(addr));
}
__device__ __forceinline__ void ldsm_x2_t(uint32_t& r0, uint32_t& r1, uint32_t addr) {
    asm volatile("ldmatrix.sync.aligned.m8n8.x2.trans.shared.b16 {%0,%1}, [%2];"
                 : "=r"(r0), "=r"(r1) : "r"(addr));
}
__device__ __forceinline__ void mma_m(float c[4], const uint32_t a[4],
                                      const uint32_t b[2]) {
    asm volatile(
        "mma.sync.aligned.m16n8k16.row.col.f32.f16.f16.f32 "
        "{%0,%1,%2,%3}, {%4,%5,%6,%7}, {%8,%9}, {%0,%1,%2,%3};"
        : "+f"(c[0]), "+f"(c[1]), "+f"(c[2]), "+f"(c[3])
        : "r"(a[0]), "r"(a[1]), "r"(a[2]), "r"(a[3]), "r"(b[0]), "r"(b[1]));
}
__device__ __forceinline__ uint32_t pack_h2(float x, float y) {
    __half2 t = __floats2half2_rn(x, y);
    return *(uint32_t*)&t;
}
__device__ __forceinline__ void cpasync16(uint32_t saddr, const void* g) {
    asm volatile("cp.async.ca.shared.global [%0], [%1], 16;" :: "r"(saddr), "l"(g));
}
__device__ __forceinline__ void cpcommit() {
    asm volatile("cp.async.commit_group;");
}
template <int N>
__device__ __forceinline__ void cpwait() {
    asm volatile("cp.async.wait_group %0;" :: "n"(N));
}

// ---------------------------------------------------------------------------
// fp32 -> fp16 convert
// ---------------------------------------------------------------------------
__global__ void cvt_kernel(const float* __restrict__ in,
                           __half* __restrict__ out, int n4) {
    int i = blockIdx.x * blockDim.x + threadIdx.x;
    if (i >= n4) return;
    float4 f = ((const float4*)in)[i];
    uint2 hh;
    hh.x = pack_h2(f.x, f.y); hh.y = pack_h2(f.z, f.w);
    ((uint2*)out)[i] = hh;
}

// ---------------------------------------------------------------------------
// guard clamp
// ---------------------------------------------------------------------------
__device__ __forceinline__ float guard_clamp(
    float v, int m, int n,
    const float* __restrict__ akmin, const float* __restrict__ akmax,
    const float* __restrict__ avmin, const float* __restrict__ avmax) {
    const int c = n >> 10;
    const int b  = m >> 11;
    const int h  = (n & 1023) >> 6;
    const int ch = n & 63;
    const int ai = ((b << 4) + h) * 64 + ch;
    const float amin = (c == 1) ? akmin[ai] : avmin[ai];
    const float amax = (c == 1) ? akmax[ai] : avmax[ai];
    float lo = fmaxf(v - EPS_, amin);
    float hi = fminf(v + EPS_, amax);
    lo = fminf(lo, hi);
    return fmaxf(lo, fminf(v, hi));
}

// ---------------------------------------------------------------------------
// fp16 tensor-core GEMM:  C[M,N] = A[M,K] @ B[N,K]^T + bias  (f32 accum)
// Block 128x128, 4 warps (2x2), warp tile 64x64.
// BK=32 (row stride 40 halfs = 80 B, conflict-free LDSM), 4-stage cp.async ring.
// Stage (BYTES): A@0 (10240) | B@10240; stage 20480; 4x = 81920 B.
// ---------------------------------------------------------------------------
#define GSTG    20480
#define OFF_B   10240
#define GEMM_SMEM (4 * GSTG)     // 81920 bytes -> 2 CTAs/SM

template <int MODE>
__global__ __launch_bounds__(128, 2) void gemm_f16_kernel(
    const __half* __restrict__ A, const __half* __restrict__ Bm,
    const float* __restrict__ bias,
    float* __restrict__ C, __half* __restrict__ Ch,
    int M, int N, int K,
    const float* __restrict__ akmin, const float* __restrict__ akmax,
    const float* __restrict__ avmin, const float* __restrict__ avmax)
{
    extern __shared__ __half smem[];

    const int tid  = threadIdx.x;
    const int wid  = tid >> 5;
    const int lane = tid & 31;
    const int warp_m = (wid & 1) * 64;
    const int warp_n = (wid >> 1) * 64;
    const int bm = blockIdx.y * 128;
    const int bn = blockIdx.x * 128;

    const int KS = K >> 5;     // 32
    const uint32_t sb0 = smem_u32(smem);

    auto load_stage = [&](int ks, int buf) {
        const uint32_t sb = sb0 + buf * GSTG;
        const int k0 = ks * 32;
#pragma unroll
        for (int i = 0; i < 4; i++) {
            const int chk = tid + i * 128;          // 0..511
            const int r = chk >> 2, c = (chk & 3) * 8;
            const uint32_t sa = sb + (r * 40 + c) * 2;
            cpasync16(sa,         A  + (size_t)(bm + r) * K + k0 + c);
            cpasync16(sa + OFF_B, Bm + (size_t)(bn + r) * K + k0 + c);
        }
        cpcommit();
    };

    float c[4][8][4];
#pragma unroll
    for (int mt = 0; mt < 4; mt++)
#pragma unroll
        for (int nt = 0; nt < 8; nt++)
#pragma unroll
            for (int e = 0; e < 4; e++) c[mt][nt][e] = 0.0f;

    load_stage(0, 0);
    load_stage(1, 1);
    load_stage(2, 2);

    const int ar = lane & 15, ac = (lane >> 4) << 3;
    const int br = lane & 7,  bc = ((lane >> 3) & 1) << 3;

    for (int ks = 0; ks < KS; ks++) {
        const int buf = ks & 3;
        cpwait<2>();
        __syncthreads();
        const uint32_t sb = sb0 + buf * GSTG;

#pragma unroll
        for (int ksub = 0; ksub < 2; ksub++) {
            uint32_t af[4][4];
#pragma unroll
            for (int mt = 0; mt < 4; mt++) {
                const uint32_t aoff =
                    ((warp_m + mt * 16 + ar) * 40 + ksub * 16 + ac) * 2;
                ldsm_x4(af[mt][0], af[mt][1], af[mt][2], af[mt][3], sb + aoff);
            }
#pragma unroll
            for (int nt = 0; nt < 8; nt++) {
                uint32_t bh[2];
                const uint32_t boff =
                    OFF_B + ((warp_n + nt * 8 + br) * 40 + ksub * 16 + bc) * 2;
                ldsm_x2(bh[0], bh[1], sb + boff);
#pragma unroll
                for (int mt = 0; mt < 4; mt++)
                    mma_m(c[mt][nt], af[mt], bh);
            }
        }
        if (ks + 3 < KS) load_stage(ks + 3, (ks + 3) & 3);
        else cpcommit();   // keep commit-count advancing for the tail
    }

    // Epilogue
    const int g = lane >> 2, t = lane & 3;
#pragma unroll
    for (int mt = 0; mt < 4; mt++) {
#pragma unroll
        for (int nt = 0; nt < 8; nt++) {
            const int n0 = bn + warp_n + nt * 8 + t * 2;
            const float b0 = bias[n0], b1 = bias[n0 + 1];
#pragma unroll
            for (int half = 0; half < 2; half++) {
                const int m = bm + warp_m + mt * 16 + g + half * 8;
                float v0 = c[mt][nt][half * 2 + 0] + b0;
                float v1 = c[mt][nt][half * 2 + 1] + b1;
                if (MODE == 1) {
                    if ((n0 >> 10) == 0) { v0 *= 0.125f; v1 *= 0.125f; }
                    else {
                        v0 = guard_clamp(v0, m, n0,     akmin, akmax, avmin, avmax);
                        v1 = guard_clamp(v1, m, n0 + 1, akmin, akmax, avmin, avmax);
                    }
                    *(uint32_t*)&Ch[(size_t)m * N + n0] = pack_h2(v0, v1);
                } else {
                    *(float2*)&C[(size_t)m * N + n0] = make_float2(v0, v1);
                }
            }
        }
    }
}

// ---------------------------------------------------------------------------
// fp16 tensor-core flash attention (f32 accumulators).
// cp.async double-buffered K/V, ONE __syncthreads per kv-tile.
// smem: Q[64][72] + 2 x (K[64][72], V[64][72]) fp16 = 46080 B.
// ---------------------------------------------------------------------------
#define STR_ 72
#define KVSZ (64 * STR_)          // halfs per tile array

__global__ __launch_bounds__(128) void attn_tc_kernel(
    const __half* __restrict__ qkv, __half* __restrict__ oh)
{
    extern __shared__ __half sb[];
    __half* sQ = sb;                       // 64*72
    __half* sK0 = sQ + KVSZ;
    __half* sV0 = sK0 + KVSZ;
    __half* sK1 = sV0 + KVSZ;
    __half* sV1 = sK1 + KVSZ;

    const int qt = blockIdx.x, h = blockIdx.y, b = blockIdx.z;
    const int tid = threadIdx.x, w = tid >> 5, lane = tid & 31;
    const int g = lane >> 2, t = lane & 3;

    // issue K/V load for kt=0 into buffer 0 (cp.async, no wait yet)
    auto load_kv = [&](int kt, __half* dK, __half* dV) {
#pragma unroll
        for (int i = 0; i < 4; i++) {
            const int chk = tid + i * 128;       // 0..511
            const int r = chk >> 3, c8 = (chk & 7) << 3;
            const size_t gb =
                ((size_t)(b * S_ + kt * 64 + r) * 3) * 1024 + h * 64 + c8;
            cpasync16(smem_u32(dK + r * STR_ + c8), qkv + gb + 1024);
            cpasync16(smem_u32(dV + r * STR_ + c8), qkv + gb + 2048);
        }
        cpcommit();
    };
    load_kv(0, sK0, sV0);

    // load Q tile (plain), hoist fragments
#pragma unroll
    for (int it = 0; it < 4; it++) {
        const int idx = tid + it * 128;
        const int r = idx >> 3, c8 = (idx & 7) << 3;
        const size_t gb = ((size_t)(b * S_ + qt * 64 + r) * 3) * 1024 + h * 64 + c8;
        *(uint4*)&sQ[r * STR_ + c8] = *(const uint4*)(qkv + gb);
    }
    __syncthreads();

    uint32_t aq[4][4];
    const int ar = lane & 15, ac8 = (lane >> 4) << 3;
#pragma unroll
    for (int k = 0; k < 4; k++) {
        const int roff = (w * 16 + ar) * STR_ + ac8 + k * 16;
        ldsm_x4(aq[k][0], aq[k][1], aq[k][2], aq[k][3], smem_u32(&sQ[roff]));
    }

    float o[8][4];
#pragma unroll
    for (int dt = 0; dt < 8; dt++)
#pragma unroll
        for (int e = 0; e < 4; e++) o[dt][e] = 0.0f;
    float m0 = -1e30f, m1 = -1e30f, l0 = 0.0f, l1 = 0.0f;

    const int kr = lane & 7, kc = ((lane >> 3) & 1) << 3;
    const int vr = lane & 15;

    for (int kt = 0; kt < S_ / 64; kt++) {
        cpwait<0>();            // current buffer's load complete
        __syncthreads();        // + all warps done reading the other buffer
        const __half* cK = (kt & 1) ? sK1 : sK0;
        const __half* cV = (kt & 1) ? sV1 : sV0;
        if (kt + 1 < S_ / 64)
            load_kv(kt + 1, (kt & 1) ? sK0 : sK1, (kt & 1) ? sV0 : sV1);
        else
            cpcommit();

        // ---- S = Q @ K^T ----
        float sc[8][4];
#pragma unroll
        for (int nt = 0; nt < 8; nt++)
#pragma unroll
            for (int e = 0; e < 4; e++) sc[nt][e] = 0.0f;
#pragma unroll
        for (int k = 0; k < 4; k++) {
#pragma unroll
            for (int nt = 0; nt < 8; nt++) {
                uint32_t bh[2];
                const int boff = (nt * 8 + kr) * STR_ + kc + k * 16;
                ldsm_x2(bh[0], bh[1], smem_u32(cK + boff));
                mma_m(sc[nt], aq[k], bh);
            }
        }

        // ---- online softmax ----
        float mx0 = -1e30f, mx1 = -1e30f;
#pragma unroll
        for (int nt = 0; nt < 8; nt++) {
            mx0 = fmaxf(mx0, fmaxf(sc[nt][0], sc[nt][1]));
            mx1 = fmaxf(mx1, fmaxf(sc[nt][2], sc[nt][3]));
        }
        mx0 = fmaxf(mx0, __shfl_xor_sync(0xffffffffu, mx0, 1));
        mx0 = fmaxf(mx0, __shfl_xor_sync(0xffffffffu, mx0, 2));
        mx1 = fmaxf(mx1, __shfl_xor_sync(0xffffffffu, mx1, 1));
        mx1 = fmaxf(mx1, __shfl_xor_sync(0xffffffffu, mx1, 2));
        const float mn0 = fmaxf(m0, mx0), mn1 = fmaxf(m1, mx1);
        const float c0 = __expf(m0 - mn0), c1 = __expf(m1 - mn1);
        float rs0 = 0.0f, rs1 = 0.0f;
#pragma unroll
        for (int nt = 0; nt < 8; nt++) {
            sc[nt][0] = __expf(sc[nt][0] - mn0);
            sc[nt][1] = __expf(sc[nt][1] - mn0);
            sc[nt][2] = __expf(sc[nt][2] - mn1);
            sc[nt][3] = __expf(sc[nt][3] - mn1);
            rs0 += sc[nt][0] + sc[nt][1];
            rs1 += sc[nt][2] + sc[nt][3];
        }
        rs0 += __shfl_xor_sync(0xffffffffu, rs0, 1);
        rs0 += __shfl_xor_sync(0xffffffffu, rs0, 2);
        rs1 += __shfl_xor_sync(0xffffffffu, rs1, 1);
        rs1 += __shfl_xor_sync(0xffffffffu, rs1, 2);
        l0 = l0 * c0 + rs0;
        l1 = l1 * c1 + rs1;
        m0 = mn0; m1 = mn1;
#pragma unroll
        for (int dt = 0; dt < 8; dt++) {
            o[dt][0] *= c0; o[dt][1] *= c0;
            o[dt][2] *= c1; o[dt][3] *= c1;
        }

        // ---- O += P @ V ----
#pragma unroll
        for (int kq = 0; kq < 4; kq++) {
            uint32_t ph[4];
            ph[0] = pack_h2(sc[2 * kq][0], sc[2 * kq][1]);
            ph[1] = pack_h2(sc[2 * kq][2], sc[2 * kq][3]);
            ph[2] = pack_h2(sc[2 * kq + 1][0], sc[2 * kq + 1][1]);
            ph[3] = pack_h2(sc[2 * kq + 1][2], sc[2 * kq + 1][3]);
#pragma unroll
            for (int dt = 0; dt < 8; dt++) {
                uint32_t bv[2];
                const int voff = (kq * 16 + vr) * STR_ + dt * 8;
                ldsm_x2_t(bv[0], bv[1], smem_u32(cV + voff));
                mma_m(o[dt], ph, bv);
            }
        }
    }

    const float inv0 = 1.0f / l0, inv1 = 1.0f / l1;
    const int r0 = qt * 64 + w * 16 + g;
    const int r1 = r0 + 8;
#pragma unroll
    for (int dt = 0; dt < 8; dt++) {
        const int d0 = h * 64 + dt * 8 + t * 2;
        *(uint32_t*)&oh[(size_t)(b * S_ + r0) * 1024 + d0] =
            pack_h2(o[dt][0] * inv0, o[dt][1] * inv0);
        *(uint32_t*)&oh[(size_t)(b * S_ + r1) * 1024 + d0] =
            pack_h2(o[dt][2] * inv1, o[dt][3] * inv1);
    }
}

// ---------------------------------------------------------------------------
extern "C" void kernel_launch(void* const* d_in, const int* in_sizes, int n_in,
                              void* d_out, int out_size)
{
    const float* x      = (const float*)d_in[0];
    const float* qkv_w  = (const float*)d_in[1];
    const float* qkv_b  = (const float*)d_in[2];
    const float* out_w  = (const float*)d_in[3];
    const float* out_b  = (const float*)d_in[4];
    const float* akmin  = (const float*)d_in[5];
    const float* akmax  = (const float*)d_in[6];
    const float* avmin  = (const float*)d_in[7];
    const float* avmax  = (const float*)d_in[8];
    float* out = (float*)d_out;

    __half *qkv, *a, *wq, *wo;
    cudaGetSymbolAddress((void**)&qkv, g_qkv);
    cudaGetSymbolAddress((void**)&a,   g_a);
    cudaGetSymbolAddress((void**)&wq,  g_wq);
    cudaGetSymbolAddress((void**)&wo,  g_wo);

    const int attn_smem = 5 * KVSZ * (int)sizeof(__half);   // 46080
    cudaFuncSetAttribute(gemm_f16_kernel<1>,
                         cudaFuncAttributeMaxDynamicSharedMemorySize, GEMM_SMEM);
    cudaFuncSetAttribute(gemm_f16_kernel<0>,
                         cudaFuncAttributeMaxDynamicSharedMemorySize, GEMM_SMEM);
    cudaFuncSetAttribute(attn_tc_kernel,
                         cudaFuncAttributeMaxDynamicSharedMemorySize, attn_smem);

    // 0) fp32 -> fp16 converts
    cvt_kernel<<<(M_ROWS * D_ / 4 + 255) / 256, 256>>>(x, a, M_ROWS * D_ / 4);
    cvt_kernel<<<(N_QKV * D_ / 4 + 255) / 256, 256>>>(qkv_w, wq, N_QKV * D_ / 4);
    cvt_kernel<<<(D_ * D_ / 4 + 255) / 256, 256>>>(out_w, wo, D_ * D_ / 4);

    // 1) QKV projection + bias + q-scale + guard-clamp -> fp16 QKV
    {
        dim3 grid(N_QKV / 128, M_ROWS / 128);   // 24 x 32
        gemm_f16_kernel<1><<<grid, 128, GEMM_SMEM>>>(
            a, wq, qkv_b, nullptr, qkv, M_ROWS, N_QKV, D_,
            akmin, akmax, avmin, avmax);
    }

    // 2) Tensor-core flash attention (fp16 out into a)
    {
        dim3 grid(S_ / 64, H_, B_);
        attn_tc_kernel<<<grid, 128, attn_smem>>>(qkv, a);
    }

    // 3) Output projection (fp32 result)
    {
        dim3 grid(D_ / 128, M_ROWS / 128);      // 8 x 32
        gemm_f16_kernel<0><<<grid, 128, GEMM_SMEM>>>(
            a, wo, out_b, out, nullptr, M_ROWS, D_, D_,
            nullptr, nullptr, nullptr, nullptr);
    }
}